// round 6
// baseline (speedup 1.0000x reference)
#include <cuda_runtime.h>

// 3x3 VALID conv, 8192x8192 fp32 in -> 8190x8190 fp32 out, + scalar bias.
// R3 finding: DRAM traffic already minimal (~515MB) but L1tex at 70% was the
// binder (each sector fetched twice). R4: 8 cols/thread, exact 2xLDG.128 per
// row (no overlap) + 2-element halo via warp shuffle. Halves L1 load wavefronts.

#define IW 8192
#define OW 8190
#define OH 8190
#define RPT 16   // output rows per thread (18 row-loads / 16 rows)
#define TPB 128  // threads/block; 8 cols/thread -> 1024 cols/block

__global__ __launch_bounds__(TPB) void Conv2D_35210141892837_kernel(
    const float* __restrict__ x,
    const float* __restrict__ wgt,
    const float* __restrict__ bias,
    float* __restrict__ out)
{
    const int tid  = threadIdx.x;
    const int lane = tid & 31;
    const int c  = (blockIdx.x * TPB + tid) * 8;   // output col base (max 8184 < OW)
    const int r0 = blockIdx.y * RPT;               // output row base (max 8176 < OH)

    const float w00 = wgt[0], w01 = wgt[1], w02 = wgt[2];
    const float w10 = wgt[3], w11 = wgt[4], w12 = wgt[5];
    const float w20 = wgt[6], w21 = wgt[7], w22 = wgt[8];
    const float bv  = bias[0];

    // partial: only the very last thread per row (c==8184) -> 6 outputs, no halo.
    const bool partial  = (c + 8 > OW);
    // lane 31 can't shuffle from next warp; it loads its halo directly.
    const bool halo_ld  = (lane == 31) && !partial;

    // Three rotating 10-float row buffers: [0..7] = own 8 floats, [8..9] = halo.
    float buf[3][10];

    // Convergent row loader (shuffles require full-warp participation).
    auto load_row = [&](int rr, float* d) {
        const float* p = x + (size_t)rr * IW + c;
        float4 a = *(const float4*)(p);
        float4 b = *(const float4*)(p + 4);
        float h0 = __shfl_down_sync(0xffffffffu, a.x, 1);
        float h1 = __shfl_down_sync(0xffffffffu, a.y, 1);
        if (halo_ld) {                       // cols c+8, c+9 (<= 8185, in-bounds)
            float2 e = *(const float2*)(p + 8);
            h0 = e.x; h1 = e.y;
        }
        d[0]=a.x; d[1]=a.y; d[2]=a.z; d[3]=a.w;
        d[4]=b.x; d[5]=b.y; d[6]=b.z; d[7]=b.w;
        d[8]=h0;  d[9]=h1;
    };

    // Preload input rows r0, r0+1 (r0 <= 8176, in-bounds).
    load_row(r0,     buf[0]);
    load_row(r0 + 1, buf[1]);

    const bool row_full = (r0 + RPT <= OH);

    if (row_full) {
        #pragma unroll
        for (int i = 0; i < RPT; i++) {
            const int r = r0 + i;
            load_row(r + 2, buf[(i + 2) % 3]);     // r+2 <= 8191, in-bounds
            const float* t = buf[ i      % 3];
            const float* m = buf[(i + 1) % 3];
            const float* l = buf[(i + 2) % 3];

            float o[8];
            #pragma unroll
            for (int j = 0; j < 8; j++) {
                float acc = bv;
                acc = fmaf(w00, t[j],   acc); acc = fmaf(w01, t[j+1], acc); acc = fmaf(w02, t[j+2], acc);
                acc = fmaf(w10, m[j],   acc); acc = fmaf(w11, m[j+1], acc); acc = fmaf(w12, m[j+2], acc);
                acc = fmaf(w20, l[j],   acc); acc = fmaf(w21, l[j+1], acc); acc = fmaf(w22, l[j+2], acc);
                o[j] = acc;
            }

            // Output stride 8190 floats is only 8B-aligned -> float2 stores.
            float* po = out + (size_t)r * OW + c;
            *(float2*)(po)     = make_float2(o[0], o[1]);
            *(float2*)(po + 2) = make_float2(o[2], o[3]);
            *(float2*)(po + 4) = make_float2(o[4], o[5]);
            if (!partial)
                *(float2*)(po + 6) = make_float2(o[6], o[7]);
        }
    } else {
        // Last row-block: per-row guard (warp-uniform, shuffles stay convergent).
        #pragma unroll
        for (int i = 0; i < RPT; i++) {
            const int r = r0 + i;
            if (r >= OH) break;
            load_row(r + 2, buf[(i + 2) % 3]);
            const float* t = buf[ i      % 3];
            const float* m = buf[(i + 1) % 3];
            const float* l = buf[(i + 2) % 3];

            float o[8];
            #pragma unroll
            for (int j = 0; j < 8; j++) {
                float acc = bv;
                acc = fmaf(w00, t[j],   acc); acc = fmaf(w01, t[j+1], acc); acc = fmaf(w02, t[j+2], acc);
                acc = fmaf(w10, m[j],   acc); acc = fmaf(w11, m[j+1], acc); acc = fmaf(w12, m[j+2], acc);
                acc = fmaf(w20, l[j],   acc); acc = fmaf(w21, l[j+1], acc); acc = fmaf(w22, l[j+2], acc);
                o[j] = acc;
            }

            float* po = out + (size_t)r * OW + c;
            *(float2*)(po)     = make_float2(o[0], o[1]);
            *(float2*)(po + 2) = make_float2(o[2], o[3]);
            *(float2*)(po + 4) = make_float2(o[4], o[5]);
            if (!partial)
                *(float2*)(po + 6) = make_float2(o[6], o[7]);
        }
    }
}

extern "C" void kernel_launch(void* const* d_in, const int* in_sizes, int n_in,
                              void* d_out, int out_size) {
    const float* x    = (const float*)d_in[0];
    const float* wgt  = (const float*)d_in[1];
    const float* bias = (const float*)d_in[2];
    float* out = (float*)d_out;

    dim3 block(TPB, 1, 1);
    dim3 grid(IW / (TPB * 8),                 // 8 blocks cover 8192 cols
              (OH + RPT - 1) / RPT,           // 512
              1);
    Conv2D_35210141892837_kernel<<<grid, block>>>(x, wgt, bias, out);
}

// round 8
// speedup vs baseline: 1.2722x; 1.2722x over previous
#include <cuda_runtime.h>

// 3x3 VALID conv, 8192x8192 fp32 in -> 8190x8190 fp32 out, + scalar bias.
// R3: 126us, DRAM 51.5%, L1 70% (fetch amp 2.0x/col, regs=32 -> no MLP).
// R4 (shuffles) regressed: SHFL lives on the L1TEX/MIO pipe. Reverted.
// R6 design: 12 cols/thread, 4xLDG.128/row (amp 1.33x/col), 4-deep rotating
// row buffers with prefetch distance 1 to hide DRAM latency behind FMAs.

#define IW 8192
#define OW 8190
#define OH 8190
#define RPT 16   // output rows per thread
#define TPB 128  // threads/block; 12 cols/thread -> 1536 cols/block
#define NC  12   // output cols per thread

__global__ __launch_bounds__(TPB) void Conv2D_35210141892837_kernel(
    const float* __restrict__ x,
    const float* __restrict__ wgt,
    const float* __restrict__ bias,
    float* __restrict__ out)
{
    const int c  = (blockIdx.x * TPB + threadIdx.x) * NC;  // output col base
    const int r0 = blockIdx.y * RPT;                       // output row base
    if (c >= OW) return;

    const float w00 = wgt[0], w01 = wgt[1], w02 = wgt[2];
    const float w10 = wgt[3], w11 = wgt[4], w12 = wgt[5];
    const float w20 = wgt[6], w21 = wgt[7], w22 = wgt[8];
    const float bv  = bias[0];

    const bool row_full = (r0 + RPT <= OH);

    // Full path requires reading 16 floats at c (c+16 <= IW) and writing 12
    // outputs (c+12 <= OW). c is a multiple of 12; both hold iff c <= 8172.
    if (c + 16 <= IW && c + NC <= OW) {
        // Four rotating 16-float row buffers (prefetch distance 1).
        float buf[4][16];

        auto load16 = [&](int rr, float* d) {
            const float* p = x + (size_t)rr * IW + c;
            float4 a = *(const float4*)(p);
            float4 b = *(const float4*)(p + 4);
            float4 e = *(const float4*)(p + 8);
            float4 f = *(const float4*)(p + 12);
            d[0]=a.x;  d[1]=a.y;  d[2]=a.z;  d[3]=a.w;
            d[4]=b.x;  d[5]=b.y;  d[6]=b.z;  d[7]=b.w;
            d[8]=e.x;  d[9]=e.y;  d[10]=e.z; d[11]=e.w;
            d[12]=f.x; d[13]=f.y; d[14]=f.z; d[15]=f.w;
        };

        // Preload input rows r0..r0+2 (r0 <= 8176, so r0+2 <= 8178 in-bounds).
        load16(r0,     buf[0]);
        load16(r0 + 1, buf[1]);
        load16(r0 + 2, buf[2]);

        if (row_full) {
            #pragma unroll
            for (int i = 0; i < RPT; i++) {
                const int r = r0 + i;
                // Prefetch row r+3 (used next iteration). Max r0+17 <= 8177.
                if (i < RPT - 1) load16(r + 3, buf[(i + 3) & 3]);

                const float* t = buf[ i      & 3];
                const float* m = buf[(i + 1) & 3];
                const float* l = buf[(i + 2) & 3];

                float o[NC];
                #pragma unroll
                for (int j = 0; j < NC; j++) {
                    float acc = bv;
                    acc = fmaf(w00, t[j],   acc); acc = fmaf(w01, t[j+1], acc); acc = fmaf(w02, t[j+2], acc);
                    acc = fmaf(w10, m[j],   acc); acc = fmaf(w11, m[j+1], acc); acc = fmaf(w12, m[j+2], acc);
                    acc = fmaf(w20, l[j],   acc); acc = fmaf(w21, l[j+1], acc); acc = fmaf(w22, l[j+2], acc);
                    o[j] = acc;
                }

                // Output row stride 8190 floats is only 8B-aligned -> float2 stores.
                float* po = out + (size_t)r * OW + c;
                *(float2*)(po)      = make_float2(o[0],  o[1]);
                *(float2*)(po + 2)  = make_float2(o[2],  o[3]);
                *(float2*)(po + 4)  = make_float2(o[4],  o[5]);
                *(float2*)(po + 6)  = make_float2(o[6],  o[7]);
                *(float2*)(po + 8)  = make_float2(o[8],  o[9]);
                *(float2*)(po + 10) = make_float2(o[10], o[11]);
            }
        } else {
            // Tail row block (r0 = 8176, 14 rows): guard compute and prefetch.
            #pragma unroll
            for (int i = 0; i < RPT; i++) {
                const int r = r0 + i;
                if (r >= OH) break;
                if (i < RPT - 1 && r + 3 <= IW - 1) load16(r + 3, buf[(i + 3) & 3]);

                const float* t = buf[ i      & 3];
                const float* m = buf[(i + 1) & 3];
                const float* l = buf[(i + 2) & 3];

                float o[NC];
                #pragma unroll
                for (int j = 0; j < NC; j++) {
                    float acc = bv;
                    acc = fmaf(w00, t[j],   acc); acc = fmaf(w01, t[j+1], acc); acc = fmaf(w02, t[j+2], acc);
                    acc = fmaf(w10, m[j],   acc); acc = fmaf(w11, m[j+1], acc); acc = fmaf(w12, m[j+2], acc);
                    acc = fmaf(w20, l[j],   acc); acc = fmaf(w21, l[j+1], acc); acc = fmaf(w22, l[j+2], acc);
                    o[j] = acc;
                }

                float* po = out + (size_t)r * OW + c;
                *(float2*)(po)      = make_float2(o[0],  o[1]);
                *(float2*)(po + 2)  = make_float2(o[2],  o[3]);
                *(float2*)(po + 4)  = make_float2(o[4],  o[5]);
                *(float2*)(po + 6)  = make_float2(o[6],  o[7]);
                *(float2*)(po + 8)  = make_float2(o[8],  o[9]);
                *(float2*)(po + 10) = make_float2(o[10], o[11]);
            }
        }
    } else {
        // Column-boundary thread (c == 8184): 6 outputs, inputs c..c+7
        // (2x float4, aligned, in-bounds). Negligible thread count.
        for (int i = 0; i < RPT; i++) {
            const int r = r0 + i;
            if (r >= OH) break;
            const float* p0 = x + (size_t)r * IW + c;
            const float* p1 = p0 + IW;
            const float* p2 = p1 + IW;
            float t[8], m[8], l[8];
            *(float4*)(t)   = *(const float4*)(p0);
            *(float4*)(t+4) = *(const float4*)(p0 + 4);
            *(float4*)(m)   = *(const float4*)(p1);
            *(float4*)(m+4) = *(const float4*)(p1 + 4);
            *(float4*)(l)   = *(const float4*)(p2);
            *(float4*)(l+4) = *(const float4*)(p2 + 4);
            #pragma unroll
            for (int j = 0; j < 6; j++) {
                const int col = c + j;
                if (col >= OW) break;
                float acc = bv;
                acc = fmaf(w00, t[j],   acc); acc = fmaf(w01, t[j+1], acc); acc = fmaf(w02, t[j+2], acc);
                acc = fmaf(w10, m[j],   acc); acc = fmaf(w11, m[j+1], acc); acc = fmaf(w12, m[j+2], acc);
                acc = fmaf(w20, l[j],   acc); acc = fmaf(w21, l[j+1], acc); acc = fmaf(w22, l[j+2], acc);
                out[(size_t)r * OW + col] = acc;
            }
        }
    }
}

extern "C" void kernel_launch(void* const* d_in, const int* in_sizes, int n_in,
                              void* d_out, int out_size) {
    const float* x    = (const float*)d_in[0];
    const float* wgt  = (const float*)d_in[1];
    const float* bias = (const float*)d_in[2];
    float* out = (float*)d_out;

    dim3 block(TPB, 1, 1);
    dim3 grid((OW + TPB * NC - 1) / (TPB * NC),   // 6
              (OH + RPT - 1) / RPT,               // 512
              1);
    Conv2D_35210141892837_kernel<<<grid, block>>>(x, wgt, bias, out);
}

// round 10
// speedup vs baseline: 2.5376x; 1.9947x over previous
#include <cuda_runtime.h>

// 3x3 VALID conv, 8192x8192 fp32 in -> 8190x8190 fp32 out, + scalar bias.
// R3 (126us, occ 86%, L1 70%, DRAM 51%) is the anchor. R4/R6 proved occupancy
// is king here (regs>48 -> regression). R8 keeps R3's shape (4 cols/thread,
// regs ~36) and only fixes the store path: parity-shifted 16B-aligned STG.128
// (s = 0 on even rows, 2 on odd rows; compile-time per unrolled iteration),
// halving store L1 wavefronts at zero register cost.

#define IW 8192
#define OW 8190
#define OH 8190
#define RPT 16   // output rows per thread; even -> row parity == i parity
#define TPB 128  // threads/block; 4 cols/thread -> 512 cols/block

__global__ __launch_bounds__(TPB, 12) void Conv2D_35210141892837_kernel(
    const float* __restrict__ x,
    const float* __restrict__ wgt,
    const float* __restrict__ bias,
    float* __restrict__ out)
{
    const int c  = (blockIdx.x * TPB + threadIdx.x) * 4;   // 0..8188
    const int r0 = blockIdx.y * RPT;                       // even
    if (c >= OW) return;

    const float w00 = wgt[0], w01 = wgt[1], w02 = wgt[2];
    const float w10 = wgt[3], w11 = wgt[4], w12 = wgt[5];
    const float w20 = wgt[6], w21 = wgt[7], w22 = wgt[8];
    const float bv  = bias[0];

    // ---- edge thread c == 8188: cols 8188,8189 on even rows only ----
    if (c == 8188) {
        for (int i = 0; i < RPT; i += 2) {             // even rows: s=0
            const int r = r0 + i;
            if (r >= OH) break;
            const float* p0 = x + (size_t)r * IW + c;  // cols 8188..8191
            float4 t = *(const float4*)(p0);
            float4 m = *(const float4*)(p0 + IW);
            float4 l = *(const float4*)(p0 + 2 * IW);
            float o0 = bv, o1 = bv;
            o0 = fmaf(w00, t.x, o0); o0 = fmaf(w01, t.y, o0); o0 = fmaf(w02, t.z, o0);
            o0 = fmaf(w10, m.x, o0); o0 = fmaf(w11, m.y, o0); o0 = fmaf(w12, m.z, o0);
            o0 = fmaf(w20, l.x, o0); o0 = fmaf(w21, l.y, o0); o0 = fmaf(w22, l.z, o0);
            o1 = fmaf(w00, t.y, o1); o1 = fmaf(w01, t.z, o1); o1 = fmaf(w02, t.w, o1);
            o1 = fmaf(w10, m.y, o1); o1 = fmaf(w11, m.z, o1); o1 = fmaf(w12, m.w, o1);
            o1 = fmaf(w20, l.y, o1); o1 = fmaf(w21, l.z, o1); o1 = fmaf(w22, l.w, o1);
            *(float2*)(out + (size_t)r * OW + c) = make_float2(o0, o1); // 16B aligned
        }
        return;
    }

    // ---- main path: c in [0, 8184], loads cols c..c+7 (<= 8191, in-bounds) ----
    float buf[3][8];

    auto load8 = [&](int rr, float* d) {
        const float* p = x + (size_t)rr * IW + c;
        float4 a = *(const float4*)(p);
        float4 b = *(const float4*)(p + 4);
        d[0]=a.x; d[1]=a.y; d[2]=a.z; d[3]=a.w;
        d[4]=b.x; d[5]=b.y; d[6]=b.z; d[7]=b.w;
    };

    load8(r0,     buf[0]);
    load8(r0 + 1, buf[1]);

    const bool row_full = (r0 + RPT <= OH);

    #pragma unroll
    for (int i = 0; i < RPT; i++) {
        const int r = r0 + i;
        if (!row_full && r >= OH) break;
        load8(r + 2, buf[(i + 2) % 3]);                // r+2 <= 8191

        const float* t = buf[ i      % 3];
        const float* m = buf[(i + 1) % 3];
        const float* l = buf[(i + 2) % 3];

        const int s = (i & 1) ? 2 : 0;                 // compile-time per iter

        // Outputs at cols c+s .. c+s+3; inputs cols c+s .. c+s+5 (idx <= 7).
        float o0 = bv, o1 = bv, o2 = bv, o3 = bv;
        o0 = fmaf(w00, t[s+0], o0); o0 = fmaf(w01, t[s+1], o0); o0 = fmaf(w02, t[s+2], o0);
        o0 = fmaf(w10, m[s+0], o0); o0 = fmaf(w11, m[s+1], o0); o0 = fmaf(w12, m[s+2], o0);
        o0 = fmaf(w20, l[s+0], o0); o0 = fmaf(w21, l[s+1], o0); o0 = fmaf(w22, l[s+2], o0);
        o1 = fmaf(w00, t[s+1], o1); o1 = fmaf(w01, t[s+2], o1); o1 = fmaf(w02, t[s+3], o1);
        o1 = fmaf(w10, m[s+1], o1); o1 = fmaf(w11, m[s+2], o1); o1 = fmaf(w12, m[s+3], o1);
        o1 = fmaf(w20, l[s+1], o1); o1 = fmaf(w21, l[s+2], o1); o1 = fmaf(w22, l[s+3], o1);
        o2 = fmaf(w00, t[s+2], o2); o2 = fmaf(w01, t[s+3], o2); o2 = fmaf(w02, t[s+4], o2);
        o2 = fmaf(w10, m[s+2], o2); o2 = fmaf(w11, m[s+3], o2); o2 = fmaf(w12, m[s+4], o2);
        o2 = fmaf(w20, l[s+2], o2); o2 = fmaf(w21, l[s+3], o2); o2 = fmaf(w22, l[s+4], o2);
        o3 = fmaf(w00, t[s+3], o3); o3 = fmaf(w01, t[s+4], o3); o3 = fmaf(w02, t[s+5], o3);
        o3 = fmaf(w10, m[s+3], o3); o3 = fmaf(w11, m[s+4], o3); o3 = fmaf(w12, m[s+5], o3);
        o3 = fmaf(w20, l[s+3], o3); o3 = fmaf(w21, l[s+4], o3); o3 = fmaf(w22, l[s+5], o3);

        // (r*8190 + c + s) % 4 == 0 for both parities -> 16B-aligned STG.128.
        *(float4*)(out + (size_t)r * OW + c + s) = make_float4(o0, o1, o2, o3);

        if (s == 2 && c == 0) {
            // Odd rows: cols 0,1 not covered by the shifted windows.
            float e0 = bv, e1 = bv;
            e0 = fmaf(w00, t[0], e0); e0 = fmaf(w01, t[1], e0); e0 = fmaf(w02, t[2], e0);
            e0 = fmaf(w10, m[0], e0); e0 = fmaf(w11, m[1], e0); e0 = fmaf(w12, m[2], e0);
            e0 = fmaf(w20, l[0], e0); e0 = fmaf(w21, l[1], e0); e0 = fmaf(w22, l[2], e0);
            e1 = fmaf(w00, t[1], e1); e1 = fmaf(w01, t[2], e1); e1 = fmaf(w02, t[3], e1);
            e1 = fmaf(w10, m[1], e1); e1 = fmaf(w11, m[2], e1); e1 = fmaf(w12, m[3], e1);
            e1 = fmaf(w20, l[1], e1); e1 = fmaf(w21, l[2], e1); e1 = fmaf(w22, l[3], e1);
            *(float2*)(out + (size_t)r * OW) = make_float2(e0, e1);  // 8B aligned
        }
    }
}

extern "C" void kernel_launch(void* const* d_in, const int* in_sizes, int n_in,
                              void* d_out, int out_size) {
    const float* x    = (const float*)d_in[0];
    const float* wgt  = (const float*)d_in[1];
    const float* bias = (const float*)d_in[2];
    float* out = (float*)d_out;

    dim3 block(TPB, 1, 1);
    dim3 grid((OW + TPB * 4 - 1) / (TPB * 4),   // 16
              (OH + RPT - 1) / RPT,             // 512
              1);
    Conv2D_35210141892837_kernel<<<grid, block>>>(x, wgt, bias, out);
}